// round 10
// baseline (speedup 1.0000x reference)
#include <cuda_runtime.h>

#define BB   4
#define CC   32
#define HH   256
#define WW   256
#define SSZ  16
#define NHH  16
#define NWW  16
#define SP   256
#define NPIX 65536

__device__ float g_cent[BB][SP][CC];
__device__ float g_pnum[BB][SP][9][CC];
__device__ float g_pden[BB][SP][9];

// ---------------------------------------------------------------------------
// A: initial centroids = 16x16 block means. One block per (b, s).
// ---------------------------------------------------------------------------
__global__ void k_cent_init(const float* __restrict__ x) {
    int bs = blockIdx.x;
    int b = bs >> 8, s = bs & 255;
    int sy = s >> 4, sx = s & 15;
    int t = threadIdx.x, warp = t >> 5, lane = t & 31;
    const float* xb = x + (size_t)b * CC * NPIX;
#pragma unroll
    for (int ci = 0; ci < 4; ci++) {
        int c = warp + ci * 8;
        const float* p = xb + (size_t)c * NPIX
                       + (size_t)(sy * SSZ + (lane >> 1)) * WW
                       + sx * SSZ + (lane & 1) * 8;
        float sum = 0.f;
#pragma unroll
        for (int i = 0; i < 8; i++) sum += p[i];
#pragma unroll
        for (int o = 16; o > 0; o >>= 1)
            sum += __shfl_down_sync(0xffffffffu, sum, o);
        if (lane == 0) g_cent[b][s][c] = sum * (1.f / 256.f);
    }
}

// ---------------------------------------------------------------------------
// B: iteration 0. 288 threads. Broadcast-float4 smem; dot-form distance.
// ---------------------------------------------------------------------------
__global__ void k_iter0(const float* __restrict__ x) {
    __shared__ __align__(16) float px_sh[256][33];
    __shared__ __align__(16) float cent_sh[9][32];
    __shared__ __align__(16) float aff_sh[9][260];
    __shared__ float cnorm_sh[9];
    __shared__ float denp_sh[8][9];

    int b = blockIdx.y, s = blockIdx.x;
    int sy = s >> 4, sx = s & 15;
    int t = threadIdx.x;
    int w = t >> 5, lane = t & 31;

    if (t < 256) {
        const float* xp = x + (size_t)b * CC * NPIX
                        + (size_t)(sy * SSZ + (t >> 4)) * WW
                        + sx * SSZ + (t & 15);
#pragma unroll
        for (int c = 0; c < CC; c++) px_sh[t][c] = xp[(size_t)c * NPIX];
    }
    {
        int ny = sy + w / 3 - 1, nx = sx + w % 3 - 1;
        bool v = ((unsigned)ny < NHH) & ((unsigned)nx < NWW);
        float cv = v ? g_cent[b][ny * NWW + nx][lane] : 0.f;
        cent_sh[w][lane] = cv;
        float cn = cv * cv;
#pragma unroll
        for (int o = 16; o > 0; o >>= 1)
            cn += __shfl_down_sync(0xffffffffu, cn, o);
        if (lane == 0) cnorm_sh[w] = cn;
    }
    __syncthreads();

    if (t < 256) {
        float dot[9];
#pragma unroll
        for (int k = 0; k < 9; k++) dot[k] = 0.f;
        float pnorm = 0.f;
#pragma unroll
        for (int c4 = 0; c4 < 8; c4++) {
            int cb = c4 * 4;
            float p0 = px_sh[t][cb],     p1 = px_sh[t][cb + 1];
            float p2 = px_sh[t][cb + 2], p3 = px_sh[t][cb + 3];
            pnorm = fmaf(p0, p0, fmaf(p1, p1, fmaf(p2, p2, fmaf(p3, p3, pnorm))));
#pragma unroll
            for (int k = 0; k < 9; k++) {
                const float4 cv = *(const float4*)&cent_sh[k][cb];
                dot[k] = fmaf(p0, cv.x, fmaf(p1, cv.y, fmaf(p2, cv.z, fmaf(p3, cv.w, dot[k]))));
            }
        }
        float d[9], dmin = 3.4e38f;
#pragma unroll
        for (int k = 0; k < 9; k++) {
            int ny = sy + k / 3 - 1, nx = sx + k % 3 - 1;
            bool v = ((unsigned)ny < NHH) & ((unsigned)nx < NWW);
            d[k] = fmaf(-2.f, dot[k], pnorm) + cnorm_sh[k];
            if (v && d[k] < dmin) dmin = d[k];
        }
        float e[9], sum = 0.f;
#pragma unroll
        for (int k = 0; k < 9; k++) {
            int ny = sy + k / 3 - 1, nx = sx + k % 3 - 1;
            bool v = ((unsigned)ny < NHH) & ((unsigned)nx < NWW);
            e[k] = v ? expf(dmin - d[k]) : 0.f;
            sum += e[k];
        }
        float inv = 1.f / sum;
#pragma unroll
        for (int k = 0; k < 9; k++) aff_sh[k][t] = e[k] * inv;
    }
    __syncthreads();

    float acc[9];
#pragma unroll
    for (int k = 0; k < 9; k++) acc[k] = 0.f;
    if (t < 256) {
#pragma unroll
        for (int pg = 0; pg < 8; pg++) {
            int p = (w << 5) + (pg << 2);
            float p0 = px_sh[p][lane],     p1 = px_sh[p + 1][lane];
            float p2 = px_sh[p + 2][lane], p3 = px_sh[p + 3][lane];
#pragma unroll
            for (int k = 0; k < 9; k++) {
                const float4 a4 = *(const float4*)&aff_sh[k][p];
                acc[k] = fmaf(a4.x, p0, fmaf(a4.y, p1, fmaf(a4.z, p2, fmaf(a4.w, p3, acc[k]))));
            }
        }
        float dp[9];
#pragma unroll
        for (int k = 0; k < 9; k++) {
            float v = aff_sh[k][(w << 5) + lane];
#pragma unroll
            for (int o = 16; o > 0; o >>= 1)
                v += __shfl_down_sync(0xffffffffu, v, o);
            dp[k] = v;
        }
        if (lane == 0) {
#pragma unroll
            for (int k = 0; k < 9; k++) denp_sh[w][k] = dp[k];
        }
    }
    __syncthreads();
    float* part = &px_sh[0][0];
    if (t < 256) {
#pragma unroll
        for (int k = 0; k < 9; k++) part[(w * 9 + k) * 32 + lane] = acc[k];
    }
    __syncthreads();
    {
        int ny = sy + w / 3 - 1, nx = sx + w % 3 - 1;
        bool v = ((unsigned)ny < NHH) & ((unsigned)nx < NWW);
        if (v) {
            int ns = ny * NWW + nx;
            float num = 0.f;
#pragma unroll
            for (int ww = 0; ww < 8; ww++) num += part[(ww * 9 + w) * 32 + lane];
            g_pnum[b][ns][w][lane] = num;
            if (lane == 0) {
                float den = 0.f;
#pragma unroll
                for (int ww = 0; ww < 8; ww++) den += denp_sh[ww][w];
                g_pden[b][ns][w] = den;
            }
        }
    }
}

// ---------------------------------------------------------------------------
// D: iteration 1, fused centroid-update + softmax + direct window scatter.
// ---------------------------------------------------------------------------
__global__ void k_aff_out(const float* __restrict__ x, float* __restrict__ out) {
    __shared__ __align__(16) float px_sh[256][33];
    __shared__ __align__(16) float cent_sh[9][32];
    __shared__ float cnorm_sh[9];

    int b = blockIdx.y, s = blockIdx.x;
    int sy = s >> 4, sx = s & 15;
    int t = threadIdx.x;
    int w = t >> 5, lane = t & 31;

    if (t < 256) {
        const float* xp = x + (size_t)b * CC * NPIX
                        + (size_t)(sy * SSZ + (t >> 4)) * WW
                        + sx * SSZ + (t & 15);
#pragma unroll
        for (int c = 0; c < CC; c++) px_sh[t][c] = xp[(size_t)c * NPIX];
    }
    {
        int ny = sy + w / 3 - 1, nx = sx + w % 3 - 1;
        bool v = ((unsigned)ny < NHH) & ((unsigned)nx < NWW);
        float cv = 0.f;
        if (v) {
            int ns = ny * NWW + nx;
            float num = 0.f;
#pragma unroll
            for (int k = 0; k < 9; k++) {
                int ty = ny - (k / 3 - 1), tx = nx - (k % 3 - 1);
                if (((unsigned)ty < NHH) & ((unsigned)tx < NWW))
                    num += g_pnum[b][ns][k][lane];
            }
            float dl = 0.f;
            if (lane < 9) {
                int ty = ny - (lane / 3 - 1), tx = nx - (lane % 3 - 1);
                if (((unsigned)ty < NHH) & ((unsigned)tx < NWW))
                    dl = g_pden[b][ns][lane];
            }
#pragma unroll
            for (int o = 16; o > 0; o >>= 1)
                dl += __shfl_down_sync(0xffffffffu, dl, o);
            float den = __shfl_sync(0xffffffffu, dl, 0);
            cv = num / (den + 1e-16f);
        }
        cent_sh[w][lane] = cv;
        float cn = cv * cv;
#pragma unroll
        for (int o = 16; o > 0; o >>= 1)
            cn += __shfl_down_sync(0xffffffffu, cn, o);
        if (lane == 0) cnorm_sh[w] = cn;
    }
    __syncthreads();

    if (t < 256) {
        float dot[9];
#pragma unroll
        for (int k = 0; k < 9; k++) dot[k] = 0.f;
        float pnorm = 0.f;
#pragma unroll
        for (int c4 = 0; c4 < 8; c4++) {
            int cb = c4 * 4;
            float p0 = px_sh[t][cb],     p1 = px_sh[t][cb + 1];
            float p2 = px_sh[t][cb + 2], p3 = px_sh[t][cb + 3];
            pnorm = fmaf(p0, p0, fmaf(p1, p1, fmaf(p2, p2, fmaf(p3, p3, pnorm))));
#pragma unroll
            for (int k = 0; k < 9; k++) {
                const float4 cv = *(const float4*)&cent_sh[k][cb];
                dot[k] = fmaf(p0, cv.x, fmaf(p1, cv.y, fmaf(p2, cv.z, fmaf(p3, cv.w, dot[k]))));
            }
        }
        float d[9], dmin = 3.4e38f;
#pragma unroll
        for (int k = 0; k < 9; k++) {
            int ny = sy + k / 3 - 1, nx = sx + k % 3 - 1;
            bool v = ((unsigned)ny < NHH) & ((unsigned)nx < NWW);
            d[k] = fmaf(-2.f, dot[k], pnorm) + cnorm_sh[k];
            if (v && d[k] < dmin) dmin = d[k];
        }
        float e[9], sum = 0.f;
#pragma unroll
        for (int k = 0; k < 9; k++) {
            int ny = sy + k / 3 - 1, nx = sx + k % 3 - 1;
            bool v = ((unsigned)ny < NHH) & ((unsigned)nx < NWW);
            e[k] = v ? expf(dmin - d[k]) : 0.f;
            sum += e[k];
        }
        float inv = 1.f / sum;

        int n = (sy * SSZ + (t >> 4)) * WW + sx * SSZ + (t & 15);
        size_t obase = (size_t)b * SP * NPIX + (size_t)n;
#pragma unroll
        for (int k = 0; k < 9; k++) {
            int ny = sy + k / 3 - 1, nx = sx + k % 3 - 1;
            bool v = ((unsigned)ny < NHH) & ((unsigned)nx < NWW);
            if (v) out[obase + (size_t)(ny * NWW + nx) * NPIX] = e[k] * inv;
        }
    }
}

// ---------------------------------------------------------------------------
// E1: zero region, contiguous segments, GRID-STRIDE over the 1024 output rows
// with only 512 blocks (~3.5/SM) so the compute stream co-resides.
// Byte-disjoint from k_aff_out's windows -> safe to overlap.
// ---------------------------------------------------------------------------
__global__ void k_zero(float* __restrict__ out) {
    const float4 z = make_float4(0.f, 0.f, 0.f, 0.f);
    int t = threadIdx.x;
    for (int bs = blockIdx.x; bs < BB * SP; bs += gridDim.x) {
        int s = bs & 255;
        int sy = s >> 4, sx = s & 15;
        int ny0 = max(sy - 1, 0), ny1 = min(sy + 1, NHH - 1);
        int nx0 = max(sx - 1, 0), nx1 = min(sx + 1, NWW - 1);
        int y0 = ny0 << 4, y1 = (ny1 + 1) << 4;
        int xl4 = nx0 << 2;                   // left strip width (float4)
        int xr4 = (nx1 + 1) << 2;             // right strip start (float4)
        float4* orow = (float4*)(out + (size_t)bs * NPIX);

        int topN = y0 << 6;
#pragma unroll 4
        for (int i = t; i < topN; i += 256) __stcs(orow + i, z);
#pragma unroll 4
        for (int i = (y1 << 6) + t; i < 16384; i += 256) __stcs(orow + i, z);
        int lw = xl4, rw = 64 - xr4, pr = lw + rw;
        if (pr > 0) {
            int rows = y1 - y0, tot = rows * pr;
            for (int i = t; i < tot; i += 256) {
                int ry = i / pr, rx = i - ry * pr;
                int col = (rx < lw) ? rx : (xr4 + rx - lw);
                __stcs(orow + ((y0 + ry) << 6) + col, z);
            }
        }
    }
}

__global__ void k_tail(float* __restrict__ p, int n) {
    int i = blockIdx.x * blockDim.x + threadIdx.x;
    if (i < n) p[i] = 256.0f;
}

extern "C" void kernel_launch(void* const* d_in, const int* in_sizes, int n_in,
                              void* d_out, int out_size) {
    const float* x = (const float*)d_in[0];
    float* out = (float*)d_out;
    dim3 grid(SP, BB);

    // Side stream (low priority) for the zero-fill; compute gets high priority.
    int loPri = 0, hiPri = 0;
    cudaDeviceGetStreamPriorityRange(&loPri, &hiPri);
    cudaStream_t s2, s3;
    cudaStreamCreateWithPriority(&s2, cudaStreamNonBlocking, loPri);
    cudaStreamCreateWithPriority(&s3, cudaStreamNonBlocking, hiPri);
    cudaEvent_t e1, e2, e3;
    cudaEventCreateWithFlags(&e1, cudaEventDisableTiming);
    cudaEventCreateWithFlags(&e2, cudaEventDisableTiming);
    cudaEventCreateWithFlags(&e3, cudaEventDisableTiming);

    cudaEventRecord(e1, 0);
    cudaStreamWaitEvent(s2, e1, 0);
    cudaStreamWaitEvent(s3, e1, 0);

    k_zero<<<512, 256, 0, s2>>>(out);      // ~3.5 blocks/SM: leaves room
    cudaEventRecord(e2, s2);

    k_cent_init<<<BB * SP, 256, 0, s3>>>(x);
    k_iter0<<<grid, 288, 0, s3>>>(x);
    k_aff_out<<<grid, 288, 0, s3>>>(x, out);
    cudaEventRecord(e3, s3);

    cudaStreamWaitEvent(0, e2, 0);         // join both branches on stream 0
    cudaStreamWaitEvent(0, e3, 0);

    long long total = (long long)BB * SP * NPIX;
    if ((long long)out_size > total) {
        int tail = (int)((long long)out_size - total);
        k_tail<<<(tail + 255) / 256, 256>>>(out + total, tail);
    }

    cudaStreamCaptureStatus cs = cudaStreamCaptureStatusNone;
    cudaStreamIsCapturing(0, &cs);
    if (cs == cudaStreamCaptureStatusNone) {
        cudaEventDestroy(e1);
        cudaEventDestroy(e2);
        cudaEventDestroy(e3);
        cudaStreamDestroy(s2);
        cudaStreamDestroy(s3);
    }
}

// round 11
// speedup vs baseline: 1.0510x; 1.0510x over previous
#include <cuda_runtime.h>

#define BB   4
#define CC   32
#define HH   256
#define WW   256
#define SSZ  16
#define NHH  16
#define NWW  16
#define SP   256
#define NPIX 65536

__device__ float g_cent[BB][SP][CC];
__device__ float g_pnum[BB][SP][9][CC];
__device__ float g_pden[BB][SP][9];

// ---------------------------------------------------------------------------
// Zero-slice helper: each (b,s) output row's zero region (outside the 3x3-tile
// window) is linearized as [top band | bottom band | middle strips]; kernel
// `phase` zeroes a fixed contiguous fraction: 0:[0,2/5) 1:[2/5,3/4) 2:[3/4,1).
// Disjoint + complete across phases; disjoint from the window writes.
// ---------------------------------------------------------------------------
__device__ __forceinline__ void zero_slice(float* __restrict__ out, int bs,
                                           int phase, int t, int nthr) {
    int s = bs & 255;
    int sy = s >> 4, sx = s & 15;
    int ny0 = max(sy - 1, 0), ny1 = min(sy + 1, NHH - 1);
    int nx0 = max(sx - 1, 0), nx1 = min(sx + 1, NWW - 1);
    int y0 = ny0 << 4, y1 = (ny1 + 1) << 4;
    int xl4 = nx0 << 2, xr4 = (nx1 + 1) << 2;
    int topN = y0 << 6;
    int botN = 16384 - (y1 << 6);
    int lw = xl4, rw = 64 - xr4, pr = lw + rw;
    int midN = (y1 - y0) * pr;
    int Nz = topN + botN + midN;
    int b0 = (int)((long long)Nz * 2 / 5);
    int b1 = (int)((long long)Nz * 3 / 4);
    int a   = (phase == 0) ? 0  : (phase == 1) ? b0 : b1;
    int end = (phase == 0) ? b0 : (phase == 1) ? b1 : Nz;
    float4* orow = (float4*)(out + (size_t)bs * NPIX);
    const float4 z = make_float4(0.f, 0.f, 0.f, 0.f);
    int tb = topN + botN;
    for (int i = a + t; i < end; i += nthr) {
        int idx;
        if (i < topN) {
            idx = i;
        } else if (i < tb) {
            idx = (y1 << 6) + (i - topN);
        } else {
            int j = i - tb;
            int ry = j / pr, rx = j - ry * pr;
            int col = (rx < lw) ? rx : (xr4 + rx - lw);
            idx = ((y0 + ry) << 6) + col;
        }
        __stcs(orow + idx, z);
    }
}

// ---------------------------------------------------------------------------
// A: initial centroids = 16x16 block means + zero slice (phase 0).
// ---------------------------------------------------------------------------
__global__ void k_cent_init(const float* __restrict__ x, float* __restrict__ out) {
    int bs = blockIdx.x;
    int b = bs >> 8, s = bs & 255;
    int sy = s >> 4, sx = s & 15;
    int t = threadIdx.x, warp = t >> 5, lane = t & 31;

    zero_slice(out, bs, 0, t, 256);        // issue stores first; drain overlaps

    const float* xb = x + (size_t)b * CC * NPIX;
#pragma unroll
    for (int ci = 0; ci < 4; ci++) {
        int c = warp + ci * 8;
        const float* p = xb + (size_t)c * NPIX
                       + (size_t)(sy * SSZ + (lane >> 1)) * WW
                       + sx * SSZ + (lane & 1) * 8;
        float sum = 0.f;
#pragma unroll
        for (int i = 0; i < 8; i++) sum += p[i];
#pragma unroll
        for (int o = 16; o > 0; o >>= 1)
            sum += __shfl_down_sync(0xffffffffu, sum, o);
        if (lane == 0) g_cent[b][s][c] = sum * (1.f / 256.f);
    }
}

// ---------------------------------------------------------------------------
// B: iteration 0 + zero slice (phase 1). 288 threads.
// ---------------------------------------------------------------------------
__global__ void k_iter0(const float* __restrict__ x, float* __restrict__ out) {
    __shared__ __align__(16) float px_sh[256][33];
    __shared__ __align__(16) float cent_sh[9][32];
    __shared__ __align__(16) float aff_sh[9][260];
    __shared__ float cnorm_sh[9];
    __shared__ float denp_sh[8][9];

    int b = blockIdx.y, s = blockIdx.x;
    int sy = s >> 4, sx = s & 15;
    int t = threadIdx.x;
    int w = t >> 5, lane = t & 31;

    zero_slice(out, (b << 8) | s, 1, t, 288);

    if (t < 256) {
        const float* xp = x + (size_t)b * CC * NPIX
                        + (size_t)(sy * SSZ + (t >> 4)) * WW
                        + sx * SSZ + (t & 15);
#pragma unroll
        for (int c = 0; c < CC; c++) px_sh[t][c] = xp[(size_t)c * NPIX];
    }
    {
        int ny = sy + w / 3 - 1, nx = sx + w % 3 - 1;
        bool v = ((unsigned)ny < NHH) & ((unsigned)nx < NWW);
        float cv = v ? g_cent[b][ny * NWW + nx][lane] : 0.f;
        cent_sh[w][lane] = cv;
        float cn = cv * cv;
#pragma unroll
        for (int o = 16; o > 0; o >>= 1)
            cn += __shfl_down_sync(0xffffffffu, cn, o);
        if (lane == 0) cnorm_sh[w] = cn;
    }
    __syncthreads();

    if (t < 256) {
        float dot[9];
#pragma unroll
        for (int k = 0; k < 9; k++) dot[k] = 0.f;
        float pnorm = 0.f;
#pragma unroll
        for (int c4 = 0; c4 < 8; c4++) {
            int cb = c4 * 4;
            float p0 = px_sh[t][cb],     p1 = px_sh[t][cb + 1];
            float p2 = px_sh[t][cb + 2], p3 = px_sh[t][cb + 3];
            pnorm = fmaf(p0, p0, fmaf(p1, p1, fmaf(p2, p2, fmaf(p3, p3, pnorm))));
#pragma unroll
            for (int k = 0; k < 9; k++) {
                const float4 cv = *(const float4*)&cent_sh[k][cb];
                dot[k] = fmaf(p0, cv.x, fmaf(p1, cv.y, fmaf(p2, cv.z, fmaf(p3, cv.w, dot[k]))));
            }
        }
        float d[9], dmin = 3.4e38f;
#pragma unroll
        for (int k = 0; k < 9; k++) {
            int ny = sy + k / 3 - 1, nx = sx + k % 3 - 1;
            bool v = ((unsigned)ny < NHH) & ((unsigned)nx < NWW);
            d[k] = fmaf(-2.f, dot[k], pnorm) + cnorm_sh[k];
            if (v && d[k] < dmin) dmin = d[k];
        }
        float e[9], sum = 0.f;
#pragma unroll
        for (int k = 0; k < 9; k++) {
            int ny = sy + k / 3 - 1, nx = sx + k % 3 - 1;
            bool v = ((unsigned)ny < NHH) & ((unsigned)nx < NWW);
            e[k] = v ? expf(dmin - d[k]) : 0.f;
            sum += e[k];
        }
        float inv = 1.f / sum;
#pragma unroll
        for (int k = 0; k < 9; k++) aff_sh[k][t] = e[k] * inv;
    }
    __syncthreads();

    float acc[9];
#pragma unroll
    for (int k = 0; k < 9; k++) acc[k] = 0.f;
    if (t < 256) {
#pragma unroll
        for (int pg = 0; pg < 8; pg++) {
            int p = (w << 5) + (pg << 2);
            float p0 = px_sh[p][lane],     p1 = px_sh[p + 1][lane];
            float p2 = px_sh[p + 2][lane], p3 = px_sh[p + 3][lane];
#pragma unroll
            for (int k = 0; k < 9; k++) {
                const float4 a4 = *(const float4*)&aff_sh[k][p];
                acc[k] = fmaf(a4.x, p0, fmaf(a4.y, p1, fmaf(a4.z, p2, fmaf(a4.w, p3, acc[k]))));
            }
        }
        float dp[9];
#pragma unroll
        for (int k = 0; k < 9; k++) {
            float v = aff_sh[k][(w << 5) + lane];
#pragma unroll
            for (int o = 16; o > 0; o >>= 1)
                v += __shfl_down_sync(0xffffffffu, v, o);
            dp[k] = v;
        }
        if (lane == 0) {
#pragma unroll
            for (int k = 0; k < 9; k++) denp_sh[w][k] = dp[k];
        }
    }
    __syncthreads();
    float* part = &px_sh[0][0];
    if (t < 256) {
#pragma unroll
        for (int k = 0; k < 9; k++) part[(w * 9 + k) * 32 + lane] = acc[k];
    }
    __syncthreads();
    {
        int ny = sy + w / 3 - 1, nx = sx + w % 3 - 1;
        bool v = ((unsigned)ny < NHH) & ((unsigned)nx < NWW);
        if (v) {
            int ns = ny * NWW + nx;
            float num = 0.f;
#pragma unroll
            for (int ww = 0; ww < 8; ww++) num += part[(ww * 9 + w) * 32 + lane];
            g_pnum[b][ns][w][lane] = num;
            if (lane == 0) {
                float den = 0.f;
#pragma unroll
                for (int ww = 0; ww < 8; ww++) den += denp_sh[ww][w];
                g_pden[b][ns][w] = den;
            }
        }
    }
}

// ---------------------------------------------------------------------------
// D: iteration 1 fused (centroid update + softmax + window scatter) + zero
// slice (phase 2). 288 threads.
// ---------------------------------------------------------------------------
__global__ void k_aff_out(const float* __restrict__ x, float* __restrict__ out) {
    __shared__ __align__(16) float px_sh[256][33];
    __shared__ __align__(16) float cent_sh[9][32];
    __shared__ float cnorm_sh[9];

    int b = blockIdx.y, s = blockIdx.x;
    int sy = s >> 4, sx = s & 15;
    int t = threadIdx.x;
    int w = t >> 5, lane = t & 31;

    zero_slice(out, (b << 8) | s, 2, t, 288);

    if (t < 256) {
        const float* xp = x + (size_t)b * CC * NPIX
                        + (size_t)(sy * SSZ + (t >> 4)) * WW
                        + sx * SSZ + (t & 15);
#pragma unroll
        for (int c = 0; c < CC; c++) px_sh[t][c] = xp[(size_t)c * NPIX];
    }
    {
        int ny = sy + w / 3 - 1, nx = sx + w % 3 - 1;
        bool v = ((unsigned)ny < NHH) & ((unsigned)nx < NWW);
        float cv = 0.f;
        if (v) {
            int ns = ny * NWW + nx;
            float num = 0.f;
#pragma unroll
            for (int k = 0; k < 9; k++) {
                int ty = ny - (k / 3 - 1), tx = nx - (k % 3 - 1);
                if (((unsigned)ty < NHH) & ((unsigned)tx < NWW))
                    num += g_pnum[b][ns][k][lane];
            }
            float dl = 0.f;
            if (lane < 9) {
                int ty = ny - (lane / 3 - 1), tx = nx - (lane % 3 - 1);
                if (((unsigned)ty < NHH) & ((unsigned)tx < NWW))
                    dl = g_pden[b][ns][lane];
            }
#pragma unroll
            for (int o = 16; o > 0; o >>= 1)
                dl += __shfl_down_sync(0xffffffffu, dl, o);
            float den = __shfl_sync(0xffffffffu, dl, 0);
            cv = num / (den + 1e-16f);
        }
        cent_sh[w][lane] = cv;
        float cn = cv * cv;
#pragma unroll
        for (int o = 16; o > 0; o >>= 1)
            cn += __shfl_down_sync(0xffffffffu, cn, o);
        if (lane == 0) cnorm_sh[w] = cn;
    }
    __syncthreads();

    if (t < 256) {
        float dot[9];
#pragma unroll
        for (int k = 0; k < 9; k++) dot[k] = 0.f;
        float pnorm = 0.f;
#pragma unroll
        for (int c4 = 0; c4 < 8; c4++) {
            int cb = c4 * 4;
            float p0 = px_sh[t][cb],     p1 = px_sh[t][cb + 1];
            float p2 = px_sh[t][cb + 2], p3 = px_sh[t][cb + 3];
            pnorm = fmaf(p0, p0, fmaf(p1, p1, fmaf(p2, p2, fmaf(p3, p3, pnorm))));
#pragma unroll
            for (int k = 0; k < 9; k++) {
                const float4 cv = *(const float4*)&cent_sh[k][cb];
                dot[k] = fmaf(p0, cv.x, fmaf(p1, cv.y, fmaf(p2, cv.z, fmaf(p3, cv.w, dot[k]))));
            }
        }
        float d[9], dmin = 3.4e38f;
#pragma unroll
        for (int k = 0; k < 9; k++) {
            int ny = sy + k / 3 - 1, nx = sx + k % 3 - 1;
            bool v = ((unsigned)ny < NHH) & ((unsigned)nx < NWW);
            d[k] = fmaf(-2.f, dot[k], pnorm) + cnorm_sh[k];
            if (v && d[k] < dmin) dmin = d[k];
        }
        float e[9], sum = 0.f;
#pragma unroll
        for (int k = 0; k < 9; k++) {
            int ny = sy + k / 3 - 1, nx = sx + k % 3 - 1;
            bool v = ((unsigned)ny < NHH) & ((unsigned)nx < NWW);
            e[k] = v ? expf(dmin - d[k]) : 0.f;
            sum += e[k];
        }
        float inv = 1.f / sum;

        int n = (sy * SSZ + (t >> 4)) * WW + sx * SSZ + (t & 15);
        size_t obase = (size_t)b * SP * NPIX + (size_t)n;
#pragma unroll
        for (int k = 0; k < 9; k++) {
            int ny = sy + k / 3 - 1, nx = sx + k % 3 - 1;
            bool v = ((unsigned)ny < NHH) & ((unsigned)nx < NWW);
            if (v) out[obase + (size_t)(ny * NWW + nx) * NPIX] = e[k] * inv;
        }
    }
}

__global__ void k_tail(float* __restrict__ p, int n) {
    int i = blockIdx.x * blockDim.x + threadIdx.x;
    if (i < n) p[i] = 256.0f;
}

extern "C" void kernel_launch(void* const* d_in, const int* in_sizes, int n_in,
                              void* d_out, int out_size) {
    const float* x = (const float*)d_in[0];
    float* out = (float*)d_out;
    dim3 grid(SP, BB);

    // Single stream; zero-fill is distributed inside the compute kernels so
    // DRAM write drain overlaps compute without relying on stream concurrency.
    k_cent_init<<<BB * SP, 256>>>(x, out);
    k_iter0<<<grid, 288>>>(x, out);
    k_aff_out<<<grid, 288>>>(x, out);

    long long total = (long long)BB * SP * NPIX;
    if ((long long)out_size > total) {
        int tail = (int)((long long)out_size - total);
        k_tail<<<(tail + 255) / 256, 256>>>(out + total, tail);
    }
}

// round 12
// speedup vs baseline: 1.1134x; 1.0593x over previous
#include <cuda_runtime.h>

#define BB   4
#define CC   32
#define HH   256
#define WW   256
#define SSZ  16
#define NHH  16
#define NWW  16
#define SP   256
#define NPIX 65536

__device__ float g_cent[BB][SP][CC];
__device__ float g_pnum[BB][SP][9][CC];
__device__ float g_pden[BB][SP][9];

#define BARRIER_COMPUTE() asm volatile("bar.sync 1, 288;" ::: "memory")

// ---------------------------------------------------------------------------
// Zero-slice helper: per-(b,s) zero region linearized [top|bottom|mid strips],
// phase p zeroes third p of it. Disjoint+complete across phases; disjoint
// from the window writes.
// ---------------------------------------------------------------------------
__device__ __forceinline__ void zero_slice(float* __restrict__ out, int bs,
                                           int phase, int t, int nthr) {
    int s = bs & 255;
    int sy = s >> 4, sx = s & 15;
    int ny0 = max(sy - 1, 0), ny1 = min(sy + 1, NHH - 1);
    int nx0 = max(sx - 1, 0), nx1 = min(sx + 1, NWW - 1);
    int y0 = ny0 << 4, y1 = (ny1 + 1) << 4;
    int xl4 = nx0 << 2, xr4 = (nx1 + 1) << 2;
    int topN = y0 << 6;
    int botN = 16384 - (y1 << 6);
    int lw = xl4, rw = 64 - xr4, pr = lw + rw;
    int midN = (y1 - y0) * pr;
    int Nz = topN + botN + midN;
    int b0 = Nz / 3, b1 = (2 * Nz) / 3;
    int a   = (phase == 0) ? 0  : (phase == 1) ? b0 : b1;
    int end = (phase == 0) ? b0 : (phase == 1) ? b1 : Nz;
    float4* orow = (float4*)(out + (size_t)bs * NPIX);
    const float4 z = make_float4(0.f, 0.f, 0.f, 0.f);
    int tb = topN + botN;
    for (int i = a + t; i < end; i += nthr) {
        int idx;
        if (i < topN) {
            idx = i;
        } else if (i < tb) {
            idx = (y1 << 6) + (i - topN);
        } else {
            int j = i - tb;
            int ry = j / pr, rx = j - ry * pr;
            int col = (rx < lw) ? rx : (xr4 + rx - lw);
            idx = ((y0 + ry) << 6) + col;
        }
        __stcs(orow + idx, z);
    }
}

// ---------------------------------------------------------------------------
// A: 512 threads. t<256: centroid means. t>=256: zero warps (phase 0).
// No block-wide barriers -> streams are independent.
// ---------------------------------------------------------------------------
__global__ void k_cent_init(const float* __restrict__ x, float* __restrict__ out) {
    int bs = blockIdx.x;
    int t = threadIdx.x;
    if (t >= 256) {                        // zero warps
        zero_slice(out, bs, 0, t - 256, 256);
        return;
    }
    int b = bs >> 8, s = bs & 255;
    int sy = s >> 4, sx = s & 15;
    int warp = t >> 5, lane = t & 31;
    const float* xb = x + (size_t)b * CC * NPIX;
#pragma unroll
    for (int ci = 0; ci < 4; ci++) {
        int c = warp + ci * 8;
        const float* p = xb + (size_t)c * NPIX
                       + (size_t)(sy * SSZ + (lane >> 1)) * WW
                       + sx * SSZ + (lane & 1) * 8;
        float sum = 0.f;
#pragma unroll
        for (int i = 0; i < 8; i++) sum += p[i];
#pragma unroll
        for (int o = 16; o > 0; o >>= 1)
            sum += __shfl_down_sync(0xffffffffu, sum, o);
        if (lane == 0) g_cent[b][s][c] = sum * (1.f / 256.f);
    }
}

// ---------------------------------------------------------------------------
// B: 416 threads. t<288: iter-0 compute (named barrier 1, 288 participants).
// t>=288: zero warps (phase 1), no barriers.
// ---------------------------------------------------------------------------
__global__ void k_iter0(const float* __restrict__ x, float* __restrict__ out) {
    __shared__ __align__(16) float px_sh[256][33];
    __shared__ __align__(16) float cent_sh[9][32];
    __shared__ __align__(16) float aff_sh[9][260];
    __shared__ float cnorm_sh[9];
    __shared__ float denp_sh[8][9];

    int b = blockIdx.y, s = blockIdx.x;
    int sy = s >> 4, sx = s & 15;
    int t = threadIdx.x;

    if (t >= 288) {                        // zero warps
        zero_slice(out, (b << 8) | s, 1, t - 288, 128);
        return;
    }
    int w = t >> 5, lane = t & 31;

    if (t < 256) {
        const float* xp = x + (size_t)b * CC * NPIX
                        + (size_t)(sy * SSZ + (t >> 4)) * WW
                        + sx * SSZ + (t & 15);
#pragma unroll
        for (int c = 0; c < CC; c++) px_sh[t][c] = xp[(size_t)c * NPIX];
    }
    {
        int ny = sy + w / 3 - 1, nx = sx + w % 3 - 1;
        bool v = ((unsigned)ny < NHH) & ((unsigned)nx < NWW);
        float cv = v ? g_cent[b][ny * NWW + nx][lane] : 0.f;
        cent_sh[w][lane] = cv;
        float cn = cv * cv;
#pragma unroll
        for (int o = 16; o > 0; o >>= 1)
            cn += __shfl_down_sync(0xffffffffu, cn, o);
        if (lane == 0) cnorm_sh[w] = cn;
    }
    BARRIER_COMPUTE();

    if (t < 256) {
        float dot[9];
#pragma unroll
        for (int k = 0; k < 9; k++) dot[k] = 0.f;
        float pnorm = 0.f;
#pragma unroll
        for (int c4 = 0; c4 < 8; c4++) {
            int cb = c4 * 4;
            float p0 = px_sh[t][cb],     p1 = px_sh[t][cb + 1];
            float p2 = px_sh[t][cb + 2], p3 = px_sh[t][cb + 3];
            pnorm = fmaf(p0, p0, fmaf(p1, p1, fmaf(p2, p2, fmaf(p3, p3, pnorm))));
#pragma unroll
            for (int k = 0; k < 9; k++) {
                const float4 cv = *(const float4*)&cent_sh[k][cb];
                dot[k] = fmaf(p0, cv.x, fmaf(p1, cv.y, fmaf(p2, cv.z, fmaf(p3, cv.w, dot[k]))));
            }
        }
        float d[9], dmin = 3.4e38f;
#pragma unroll
        for (int k = 0; k < 9; k++) {
            int ny = sy + k / 3 - 1, nx = sx + k % 3 - 1;
            bool v = ((unsigned)ny < NHH) & ((unsigned)nx < NWW);
            d[k] = fmaf(-2.f, dot[k], pnorm) + cnorm_sh[k];
            if (v && d[k] < dmin) dmin = d[k];
        }
        float e[9], sum = 0.f;
#pragma unroll
        for (int k = 0; k < 9; k++) {
            int ny = sy + k / 3 - 1, nx = sx + k % 3 - 1;
            bool v = ((unsigned)ny < NHH) & ((unsigned)nx < NWW);
            e[k] = v ? expf(dmin - d[k]) : 0.f;
            sum += e[k];
        }
        float inv = 1.f / sum;
#pragma unroll
        for (int k = 0; k < 9; k++) aff_sh[k][t] = e[k] * inv;
    }
    BARRIER_COMPUTE();

    float acc[9];
#pragma unroll
    for (int k = 0; k < 9; k++) acc[k] = 0.f;
    if (t < 256) {
#pragma unroll
        for (int pg = 0; pg < 8; pg++) {
            int p = (w << 5) + (pg << 2);
            float p0 = px_sh[p][lane],     p1 = px_sh[p + 1][lane];
            float p2 = px_sh[p + 2][lane], p3 = px_sh[p + 3][lane];
#pragma unroll
            for (int k = 0; k < 9; k++) {
                const float4 a4 = *(const float4*)&aff_sh[k][p];
                acc[k] = fmaf(a4.x, p0, fmaf(a4.y, p1, fmaf(a4.z, p2, fmaf(a4.w, p3, acc[k]))));
            }
        }
        float dp[9];
#pragma unroll
        for (int k = 0; k < 9; k++) {
            float v = aff_sh[k][(w << 5) + lane];
#pragma unroll
            for (int o = 16; o > 0; o >>= 1)
                v += __shfl_down_sync(0xffffffffu, v, o);
            dp[k] = v;
        }
        if (lane == 0) {
#pragma unroll
            for (int k = 0; k < 9; k++) denp_sh[w][k] = dp[k];
        }
    }
    BARRIER_COMPUTE();
    float* part = &px_sh[0][0];
    if (t < 256) {
#pragma unroll
        for (int k = 0; k < 9; k++) part[(w * 9 + k) * 32 + lane] = acc[k];
    }
    BARRIER_COMPUTE();
    {
        int ny = sy + w / 3 - 1, nx = sx + w % 3 - 1;
        bool v = ((unsigned)ny < NHH) & ((unsigned)nx < NWW);
        if (v) {
            int ns = ny * NWW + nx;
            float num = 0.f;
#pragma unroll
            for (int ww = 0; ww < 8; ww++) num += part[(ww * 9 + w) * 32 + lane];
            g_pnum[b][ns][w][lane] = num;
            if (lane == 0) {
                float den = 0.f;
#pragma unroll
                for (int ww = 0; ww < 8; ww++) den += denp_sh[ww][w];
                g_pden[b][ns][w] = den;
            }
        }
    }
}

// ---------------------------------------------------------------------------
// D: 416 threads. t<288: fused centroid-update + softmax + window scatter.
// t>=288: zero warps (phase 2 + output tail), no barriers.
// ---------------------------------------------------------------------------
__global__ void k_aff_out(const float* __restrict__ x, float* __restrict__ out,
                          float* __restrict__ tailp, int tail_n) {
    __shared__ __align__(16) float px_sh[256][33];
    __shared__ __align__(16) float cent_sh[9][32];
    __shared__ float cnorm_sh[9];

    int b = blockIdx.y, s = blockIdx.x;
    int sy = s >> 4, sx = s & 15;
    int t = threadIdx.x;

    if (t >= 288) {                        // zero warps
        int tz = t - 288;
        zero_slice(out, (b << 8) | s, 2, tz, 128);
        if (b == 0 && s == 0) {            // fold former k_tail
            for (int i = tz; i < tail_n; i += 128) tailp[i] = 256.0f;
        }
        return;
    }
    int w = t >> 5, lane = t & 31;

    if (t < 256) {
        const float* xp = x + (size_t)b * CC * NPIX
                        + (size_t)(sy * SSZ + (t >> 4)) * WW
                        + sx * SSZ + (t & 15);
#pragma unroll
        for (int c = 0; c < CC; c++) px_sh[t][c] = xp[(size_t)c * NPIX];
    }
    {
        int ny = sy + w / 3 - 1, nx = sx + w % 3 - 1;
        bool v = ((unsigned)ny < NHH) & ((unsigned)nx < NWW);
        float cv = 0.f;
        if (v) {
            int ns = ny * NWW + nx;
            float num = 0.f;
#pragma unroll
            for (int k = 0; k < 9; k++) {
                int ty = ny - (k / 3 - 1), tx = nx - (k % 3 - 1);
                if (((unsigned)ty < NHH) & ((unsigned)tx < NWW))
                    num += g_pnum[b][ns][k][lane];
            }
            float dl = 0.f;
            if (lane < 9) {
                int ty = ny - (lane / 3 - 1), tx = nx - (lane % 3 - 1);
                if (((unsigned)ty < NHH) & ((unsigned)tx < NWW))
                    dl = g_pden[b][ns][lane];
            }
#pragma unroll
            for (int o = 16; o > 0; o >>= 1)
                dl += __shfl_down_sync(0xffffffffu, dl, o);
            float den = __shfl_sync(0xffffffffu, dl, 0);
            cv = num / (den + 1e-16f);
        }
        cent_sh[w][lane] = cv;
        float cn = cv * cv;
#pragma unroll
        for (int o = 16; o > 0; o >>= 1)
            cn += __shfl_down_sync(0xffffffffu, cn, o);
        if (lane == 0) cnorm_sh[w] = cn;
    }
    BARRIER_COMPUTE();

    if (t < 256) {
        float dot[9];
#pragma unroll
        for (int k = 0; k < 9; k++) dot[k] = 0.f;
        float pnorm = 0.f;
#pragma unroll
        for (int c4 = 0; c4 < 8; c4++) {
            int cb = c4 * 4;
            float p0 = px_sh[t][cb],     p1 = px_sh[t][cb + 1];
            float p2 = px_sh[t][cb + 2], p3 = px_sh[t][cb + 3];
            pnorm = fmaf(p0, p0, fmaf(p1, p1, fmaf(p2, p2, fmaf(p3, p3, pnorm))));
#pragma unroll
            for (int k = 0; k < 9; k++) {
                const float4 cv = *(const float4*)&cent_sh[k][cb];
                dot[k] = fmaf(p0, cv.x, fmaf(p1, cv.y, fmaf(p2, cv.z, fmaf(p3, cv.w, dot[k]))));
            }
        }
        float d[9], dmin = 3.4e38f;
#pragma unroll
        for (int k = 0; k < 9; k++) {
            int ny = sy + k / 3 - 1, nx = sx + k % 3 - 1;
            bool v = ((unsigned)ny < NHH) & ((unsigned)nx < NWW);
            d[k] = fmaf(-2.f, dot[k], pnorm) + cnorm_sh[k];
            if (v && d[k] < dmin) dmin = d[k];
        }
        float e[9], sum = 0.f;
#pragma unroll
        for (int k = 0; k < 9; k++) {
            int ny = sy + k / 3 - 1, nx = sx + k % 3 - 1;
            bool v = ((unsigned)ny < NHH) & ((unsigned)nx < NWW);
            e[k] = v ? expf(dmin - d[k]) : 0.f;
            sum += e[k];
        }
        float inv = 1.f / sum;

        int n = (sy * SSZ + (t >> 4)) * WW + sx * SSZ + (t & 15);
        size_t obase = (size_t)b * SP * NPIX + (size_t)n;
#pragma unroll
        for (int k = 0; k < 9; k++) {
            int ny = sy + k / 3 - 1, nx = sx + k % 3 - 1;
            bool v = ((unsigned)ny < NHH) & ((unsigned)nx < NWW);
            if (v) out[obase + (size_t)(ny * NWW + nx) * NPIX] = e[k] * inv;
        }
    }
}

extern "C" void kernel_launch(void* const* d_in, const int* in_sizes, int n_in,
                              void* d_out, int out_size) {
    const float* x = (const float*)d_in[0];
    float* out = (float*)d_out;
    dim3 grid(SP, BB);

    long long total = (long long)BB * SP * NPIX;
    int tail_n = (int)(((long long)out_size > total) ? ((long long)out_size - total) : 0);

    k_cent_init<<<BB * SP, 512>>>(x, out);
    k_iter0<<<grid, 416>>>(x, out);
    k_aff_out<<<grid, 416>>>(x, out, out + total, tail_n);
}